// round 1
// baseline (speedup 1.0000x reference)
#include <cuda_runtime.h>

#define NN 20000
#define NE 400000
#define FD 64
#define CT 64
#define HD 128
#define TS 6
#define KD 67     // F + 3 label channels
#define Z1S 68    // padded row stride for z1
#define ROWS_PB 16

// ---------------- scratch (static device globals; no allocation) -------------
__device__ int   g_flagA[NN];
__device__ int   g_flagB[NN];
__device__ int   g_isc[NN];
__device__ int   g_degcnt[NN];
__device__ float g_dinv[NN];
__device__ float g_selfn[NN];
__device__ float g_z1[NN * Z1S];
__device__ float g_h1[NN * HD];
__device__ float g_sv[NN];
__device__ float g_zs[NN];
__device__ unsigned long long g_packed;
__device__ float g_z2top[HD];
__device__ float g_seq[TS * HD];

// ---------------- kernels ----------------------------------------------------

__global__ void k_init() {
    int i = blockIdx.x * blockDim.x + threadIdx.x;
    if (i < NN * Z1S) g_z1[i] = 0.f;
    if (i < NN) {
        g_flagA[i] = 0; g_flagB[i] = 0; g_isc[i] = 0;
        g_degcnt[i] = 0; g_zs[i] = 0.f;
    }
    if (i < HD) g_z2top[i] = 0.f;
    if (i == 0) g_packed = 0ull;
}

__global__ void k_targets(const int* __restrict__ tgt) {
    int j = threadIdx.x;
    if (j < CT) {
        int n = tgt[j];
        g_flagA[n] = 1; g_flagB[n] = 1; g_isc[n] = 1;
    }
}

// one hop of expansion: read start-of-iteration flags (rd), write into wr
// (wr pre-initialized to rd's contents). Benign races: all stores write 1.
__global__ void k_prop(const int* __restrict__ ei, int srcIsA) {
    int e = blockIdx.x * blockDim.x + threadIdx.x;
    if (e >= NE) return;
    const int* rd = srcIsA ? g_flagA : g_flagB;
    int*       wr = srcIsA ? g_flagB : g_flagA;
    int s = ei[e], d = ei[NE + e];
    int fs = rd[s], fd = rd[d];
    if (fs) wr[d] = 1;
    if (fd) wr[s] = 1;
}

__global__ void k_copyBA() {   // A = B
    int i = blockIdx.x * blockDim.x + threadIdx.x;
    if (i < NN) g_flagA[i] = g_flagB[i];
}

__global__ void k_deg(const int* __restrict__ ei) {
    int e = blockIdx.x * blockDim.x + threadIdx.x;
    if (e >= NE) return;
    int s = ei[e], d = ei[NE + e];
    if (g_flagA[s] && g_flagA[d]) atomicAdd(&g_degcnt[d], 1);
}

__global__ void k_dinv() {
    int i = blockIdx.x * blockDim.x + threadIdx.x;
    if (i >= NN) return;
    if (g_flagA[i]) {
        float deg = (float)g_degcnt[i] + 1.0f;   // + self loop
        float di  = rsqrtf(deg);
        g_dinv[i]  = di;
        g_selfn[i] = di * di;
    } else {
        g_dinv[i]  = 0.f;
        g_selfn[i] = 0.f;
    }
}

// aggregate raw 67-dim features over edges: z1[dst] += xl[src] * enorm
// (labels ch64/ch65 handled as scalars; ch66 is identically zero)
__global__ void k_z1agg(const int* __restrict__ ei, const float* __restrict__ x) {
    int gid  = blockIdx.x * blockDim.x + threadIdx.x;
    int e    = gid >> 5;
    int lane = gid & 31;
    if (e >= NE) return;
    int s = ei[e], d = ei[NE + e];
    float w = g_dinv[s] * g_dinv[d];
    if (w == 0.f) return;
    float a0 = x[s * FD + lane];
    float a1 = x[s * FD + 32 + lane];
    atomicAdd(&g_z1[d * Z1S + lane],      a0 * w);
    atomicAdd(&g_z1[d * Z1S + 32 + lane], a1 * w);
    if (lane == 0) {
        if (g_isc[s]) atomicAdd(&g_z1[d * Z1S + 64], w);       // is_center
        else          atomicAdd(&g_z1[d * Z1S + 65], w);       // in_sub & ~is_c
    }
}

// h1 = relu((z1 + xl*selfn) @ W1 + b1); s = h1 @ W2[:,127]
__global__ void __launch_bounds__(128) k_gemm(const float* __restrict__ x,
                                              const float* __restrict__ W1,
                                              const float* __restrict__ b1,
                                              const float* __restrict__ W2) {
    int t = threadIdx.x;
    __shared__ float szrow[Z1S];
    __shared__ float sred[4];
    float rw[KD];
    #pragma unroll
    for (int k = 0; k < KD; k++) rw[k] = W1[k * HD + t];     // W1 column t in regs
    float w2c = W2[t * HD + (HD - 1)];
    float bb  = b1[t];

    int base = blockIdx.x * ROWS_PB;
    for (int r = 0; r < ROWS_PB; r++) {
        int i = base + r;
        if (t < Z1S) {
            float xl = 0.f;
            if (t < FD)       xl = x[i * FD + t];
            else if (t == 64) xl = (float)g_isc[i];
            else if (t == 65) xl = (g_flagA[i] && !g_isc[i]) ? 1.f : 0.f;
            szrow[t] = g_z1[i * Z1S + t] + xl * g_selfn[i];
        }
        __syncthreads();
        float acc = bb;
        #pragma unroll
        for (int k = 0; k < KD; k++) acc += szrow[k] * rw[k];
        float hv = fmaxf(acc, 0.f);
        g_h1[i * HD + t] = hv;
        float p = hv * w2c;
        #pragma unroll
        for (int o = 16; o > 0; o >>= 1) p += __shfl_down_sync(0xffffffffu, p, o);
        if ((t & 31) == 0) sred[t >> 5] = p;
        __syncthreads();
        if (t == 0) g_sv[i] = sred[0] + sred[1] + sred[2] + sred[3];
        __syncthreads();
    }
}

// scalar layer-2 aggregation: zs[dst] += s[src] * enorm
__global__ void k_zs(const int* __restrict__ ei) {
    int e = blockIdx.x * blockDim.x + threadIdx.x;
    if (e >= NE) return;
    int s = ei[e], d = ei[NE + e];
    float w = g_dinv[s] * g_dinv[d];
    if (w != 0.f) atomicAdd(&g_zs[d], g_sv[s] * w);
}

// sort_key = relu(zs + s*selfn) over subgraph nodes; argmax with
// first-index tiebreak via packed (value_bits, ~index) atomicMax
__global__ void k_argmax() {
    int i = blockIdx.x * blockDim.x + threadIdx.x;
    if (i >= NN) return;
    if (!g_flagA[i]) return;
    float v = g_zs[i] + g_sv[i] * g_selfn[i];
    v = fmaxf(v, 0.f);   // relu output >= 0: bits are monotone as unsigned
    unsigned long long key =
        ((unsigned long long)__float_as_uint(v) << 32) |
        (unsigned long long)(0xFFFFFFFFu - (unsigned)i);
    atomicMax(&g_packed, key);
}

// gather the top node's 128-dim pre-W2 aggregation from its in-edges
__global__ void k_z2top(const int* __restrict__ ei) {
    __shared__ int stop;
    if (threadIdx.x == 0)
        stop = (int)(0xFFFFFFFFu - (unsigned)(g_packed & 0xFFFFFFFFull));
    __syncthreads();
    int e = blockIdx.x * blockDim.x + threadIdx.x;
    if (e >= NE) return;
    int d = ei[NE + e];
    if (d != stop) return;
    int s = ei[e];
    float w = g_dinv[s] * g_dinv[d];
    if (w == 0.f) return;
    for (int c = 0; c < HD; c++)
        atomicAdd(&g_z2top[c], g_h1[s * HD + c] * w);
}

// seq[t] = relu((z2top + h1[top]*selfn[top]) @ W2 + b2)
__global__ void k_final(const float* __restrict__ W2, const float* __restrict__ b2,
                        int t) {
    __shared__ float zf[HD];
    __shared__ int stop_s;
    int tid = threadIdx.x;
    if (tid == 0)
        stop_s = (int)(0xFFFFFFFFu - (unsigned)(g_packed & 0xFFFFFFFFull));
    __syncthreads();
    int top = stop_s;
    zf[tid] = g_z2top[tid] + g_h1[top * HD + tid] * g_selfn[top];
    __syncthreads();
    float acc = b2[tid];
    #pragma unroll 8
    for (int k = 0; k < HD; k++) acc += zf[k] * W2[k * HD + tid];
    g_seq[t * HD + tid] = fmaxf(acc, 0.f);
}

// GRU over 6 steps + classifier head; single block of 384 threads
__global__ void k_gru(const float* __restrict__ Wih, const float* __restrict__ Whh,
                      const float* __restrict__ bih, const float* __restrict__ bhh,
                      const float* __restrict__ Wc1, const float* __restrict__ bc1,
                      const float* __restrict__ Wc2, const float* __restrict__ bc2,
                      float* __restrict__ out) {
    __shared__ float h[HD], xt[HD], gi[3 * HD], gh[3 * HD], hid[HD / 2];
    int j = threadIdx.x;
    if (j < HD) h[j] = 0.f;
    __syncthreads();
    for (int t = 0; t < TS; t++) {
        if (j < HD) xt[j] = g_seq[t * HD + j];
        __syncthreads();
        float a = bih[j], b = bhh[j];
        #pragma unroll 8
        for (int k = 0; k < HD; k++) {
            a += Wih[j * HD + k] * xt[k];
            b += Whh[j * HD + k] * h[k];
        }
        gi[j] = a; gh[j] = b;
        __syncthreads();
        if (j < HD) {
            float r  = 1.f / (1.f + expf(-(gi[j] + gh[j])));
            float z  = 1.f / (1.f + expf(-(gi[HD + j] + gh[HD + j])));
            float n  = tanhf(gi[2 * HD + j] + r * gh[2 * HD + j]);
            h[j] = (1.f - z) * n + z * h[j];   // each thread touches only h[j]
        }
        __syncthreads();
    }
    if (j < HD / 2) {
        float a = bc1[j];
        #pragma unroll 8
        for (int k = 0; k < HD; k++) a += h[k] * Wc1[k * (HD / 2) + j];
        hid[j] = fmaxf(a, 0.f);
    }
    __syncthreads();
    if (j == 0) {
        float a = bc2[0];
        for (int m = 0; m < HD / 2; m++) a += hid[m] * Wc2[m];
        out[0] = 1.f / (1.f + expf(-a));
    }
}

// ---------------- launch -----------------------------------------------------

extern "C" void kernel_launch(void* const* d_in, const int* in_sizes, int n_in,
                              void* d_out, int out_size) {
    const float* x   = (const float*)d_in[0];
    const int*   ei  = (const int*)  d_in[1];
    const int*   tgt = (const int*)  d_in[2];
    const float* W1  = (const float*)d_in[3];
    const float* b1  = (const float*)d_in[4];
    const float* W2  = (const float*)d_in[5];
    const float* b2  = (const float*)d_in[6];
    const float* Wih = (const float*)d_in[7];
    const float* Whh = (const float*)d_in[8];
    const float* bih = (const float*)d_in[9];
    const float* bhh = (const float*)d_in[10];
    const float* Wc1 = (const float*)d_in[11];
    const float* bc1 = (const float*)d_in[12];
    const float* Wc2 = (const float*)d_in[13];
    const float* bc2 = (const float*)d_in[14];
    float* out = (float*)d_out;

    const int gbN = (NN + 255) / 256;
    const int gbE = (NE + 255) / 256;
    const int gbI = (NN * Z1S + 255) / 256;
    const int gbW = (NE * 32) / 256;

    for (int t = 0; t < TS; t++) {
        const float* xt   = x   + (size_t)t * NN * FD;
        const int*   eit  = ei  + (size_t)t * 2 * NE;
        const int*   tgtt = tgt + (size_t)t * CT;

        k_init<<<gbI, 256>>>();
        k_targets<<<1, CT>>>(tgtt);
        k_prop<<<gbE, 256>>>(eit, 1);   // read A -> write B  (hop 1)
        k_copyBA<<<gbN, 256>>>();       // A = B
        k_prop<<<gbE, 256>>>(eit, 0);   // read B -> write A  (hop 2); in_sub = A
        k_deg<<<gbE, 256>>>(eit);
        k_dinv<<<gbN, 256>>>();
        k_z1agg<<<gbW, 256>>>(eit, xt);
        k_gemm<<<NN / ROWS_PB, 128>>>(xt, W1, b1, W2);
        k_zs<<<gbE, 256>>>(eit);
        k_argmax<<<gbN, 256>>>();
        k_z2top<<<gbE, 256>>>(eit);
        k_final<<<1, HD>>>(W2, b2, t);
    }
    k_gru<<<1, 3 * HD>>>(Wih, Whh, bih, bhh, Wc1, bc1, Wc2, bc2, out);
}